// round 1
// baseline (speedup 1.0000x reference)
#include <cuda_runtime.h>

// DynamicModel: 2-step vehicle dynamics integrator.
// B rows of 8 floats -> 3 floats out. Two tiny 12-wide scalar MLPs,
// two atan2 per iteration, 2 iterations.

#define TPB   256
#define ROWS  8

#define LFc   1.5f
#define LRc   1.4f
#define CM1c  550.0f
#define CM2c  650.0f
#define DTc   0.01f
#define GRAVc 9.8f
// MASS/IZ and C_DRIVE folded as fp32 constants
#define MIZc  (1265.0f / 2000.0f)
#define CDRV  ((float)(3.45 * 0.919 / (0.34 * 1265.0)))

__device__ __forceinline__ void load12(const float* __restrict__ p, float* r) {
    const float4* p4 = reinterpret_cast<const float4*>(p);
#pragma unroll
    for (int i = 0; i < 3; i++) {
        float4 v = __ldg(p4 + i);
        r[4 * i + 0] = v.x; r[4 * i + 1] = v.y;
        r[4 * i + 2] = v.z; r[4 * i + 3] = v.w;
    }
}

__device__ __forceinline__ float mlp12(float a,
                                       const float* w1, const float* b1,
                                       const float* w2, float b2) {
    float s = b2;
#pragma unroll
    for (int j = 0; j < 12; j++) {
        float h = fmaxf(fmaf(a, w1[j], b1[j]), 0.0f);
        s = fmaf(h, w2[j], s);
    }
    return s;
}

__global__ __launch_bounds__(TPB, 2)
void dyn_kernel(const float4* __restrict__ x4,
                const float* __restrict__ fy_w1, const float* __restrict__ fy_b1,
                const float* __restrict__ fy_w2, const float* __restrict__ fy_b2,
                const float* __restrict__ ry_w1, const float* __restrict__ ry_b1,
                const float* __restrict__ ry_w2, const float* __restrict__ ry_b2,
                const float* __restrict__ rx_w, const float* __restrict__ rx_b,
                float* __restrict__ out, int B) {
    __shared__ float stg[TPB * 3];

    // ---- weights -> registers (amortized over ROWS rows/thread) ----
    float w1f[12], b1f[12], w2f[12];
    float w1r[12], b1r[12], w2r[12];
    load12(fy_w1, w1f); load12(fy_b1, b1f); load12(fy_w2, w2f);
    load12(ry_w1, w1r); load12(ry_b1, b1r); load12(ry_w2, w2r);
    const float b2f = __ldg(fy_b2);
    const float b2r = __ldg(ry_b2);
    const float rxw = __ldg(rx_w);
    const float rxb = __ldg(rx_b);

    const int t = threadIdx.x;
    const long long block_row0 = (long long)blockIdx.x * (TPB * ROWS);

#pragma unroll
    for (int r = 0; r < ROWS; r++) {
        const long long row0 = block_row0 + (long long)r * TPB;  // first row of chunk
        const long long i = row0 + t;
        float o0 = 0.0f, o1 = 0.0f, o2 = 0.0f;

        if (i < B) {
            float4 a = __ldg(x4 + 2 * i);
            float4 b = __ldg(x4 + 2 * i + 1);
            const float pwm = a.x, theta = a.z, vx0 = a.w;
            const float vy0 = b.x, w0 = b.y, pitch = b.w;

            float st, ct;
            __sincosf(theta, &st, &ct);
            const float sp = __sinf(pitch);

            const float a_pred = (pwm > 0.0f ? CM1c : CM2c) * pwm * CDRV;
            const float vx_base = a_pred + rxb - GRAVc * sp;  // Frx const part - g*sp

#pragma unroll
            for (int it = 0; it < 2; it++) {
                const float vx = vx0 + o0;
                const float vy = vy0 + o1;
                const float w  = w0  + o2;

                const float af = theta - atan2f(fmaf(w, LFc, vy), vx);
                const float ar = atan2f(fmaf(w, LRc, -vy), vx);

                float f = mlp12(fabsf(af), w1f, b1f, w2f, b2f);
                const float Ffy = (af > 0.0f) ? f : -f;
                float g = mlp12(fabsf(ar), w1r, b1r, w2r, b2r);
                const float Fry = (ar > 0.0f) ? g : -g;

                const float vx_dot = fmaf(rxw * vx, vx, vx_base) - Ffy * st + vy * w;
                const float vy_dot = fmaf(Ffy, ct, Fry) - vx * w;
                const float w_dot  = (Ffy * (LFc * ct) - Fry * LRc) * MIZc;

                o0 = fmaf(DTc, vx_dot, o0);
                o1 = fmaf(DTc, vy_dot, o1);
                o2 = fmaf(DTc, w_dot,  o2);
            }
        }

        // ---- coalesced store via shared staging ----
        __syncthreads();            // protect buffer reuse across r
        stg[t * 3 + 0] = o0;
        stg[t * 3 + 1] = o1;
        stg[t * 3 + 2] = o2;
        __syncthreads();

        const long long base3 = row0 * 3;
        const long long lim = (long long)B * 3;
#pragma unroll
        for (int k = 0; k < 3; k++) {
            long long idx = base3 + t + k * TPB;
            if (idx < lim) out[idx] = stg[t + k * TPB];
        }
    }
}

extern "C" void kernel_launch(void* const* d_in, const int* in_sizes, int n_in,
                              void* d_out, int out_size) {
    const float* x     = (const float*)d_in[0];
    const float* fy_w1 = (const float*)d_in[1];
    const float* fy_b1 = (const float*)d_in[2];
    const float* fy_w2 = (const float*)d_in[3];
    const float* fy_b2 = (const float*)d_in[4];
    const float* ry_w1 = (const float*)d_in[5];
    const float* ry_b1 = (const float*)d_in[6];
    const float* ry_w2 = (const float*)d_in[7];
    const float* ry_b2 = (const float*)d_in[8];
    const float* rx_w  = (const float*)d_in[9];
    const float* rx_b  = (const float*)d_in[10];
    float* out = (float*)d_out;

    const int B = in_sizes[0] / 8;
    const int rows_per_block = TPB * ROWS;
    const int grid = (B + rows_per_block - 1) / rows_per_block;

    dyn_kernel<<<grid, TPB>>>((const float4*)x,
                              fy_w1, fy_b1, fy_w2, fy_b2,
                              ry_w1, ry_b1, ry_w2, ry_b2,
                              rx_w, rx_b, out, B);
}